// round 2
// baseline (speedup 1.0000x reference)
#include <cuda_runtime.h>

// EMA scan: out[b,t,d] = a*out[b,t-1,d] + (1-a)*x[b,t,d], out[b,-1,d]=0
// Shapes fixed: B=4, S=4096, D=2048, fp32. Single-pass decoupled lookback.

#define B 4
#define S 4096
#define D 2048
#define TT 32              // timesteps per chunk
#define NC (S / TT)        // 128 chunks per (b, channel)
#define DBLK 256           // channels per CTA (== blockDim.x)
#define NXB (D / DBLK)     // 8 CTAs along d

constexpr float ALPHA = 0.99f;
constexpr float ONEM  = 0.01f;

constexpr float pow_alpha(int n) {
    double r = 1.0;
    for (int i = 0; i < n; ++i) r *= 0.99;
    return (float)r;
}
constexpr float DEC = pow_alpha(TT);   // alpha^32

// Lookback state (allocation-free scratch).
// agg/incl: per-(b,chunk,channel) chunk-local end EMA / inclusive prefix. 4 MB each.
// flag:     per-(b,chunk,dblock) status: 0=none, 1=aggregate ready, 2=inclusive ready.
__device__ float g_agg [B * NC * D];
__device__ float g_incl[B * NC * D];
__device__ int   g_flag[B * NC * NXB];

// ---------------------------------------------------------------------------
// Reset flags (must run before the scan each replay: graph-deterministic).
// ---------------------------------------------------------------------------
__global__ void ema_reset() {
    int i = blockIdx.x * blockDim.x + threadIdx.x;
    if (i < B * NC * NXB) g_flag[i] = 0;
}

// ---------------------------------------------------------------------------
// Single-pass EMA scan with decoupled lookback.
// grid: (NXB, NC, B), block: DBLK. Thread owns one channel of one chunk.
// ---------------------------------------------------------------------------
__global__ void __launch_bounds__(DBLK) ema_scan(const float* __restrict__ x,
                                                 float* __restrict__ out) {
    const int tid = threadIdx.x;
    const int d = blockIdx.x * DBLK + tid;
    const int c = blockIdx.y;
    const int b = blockIdx.z;

    const size_t base = ((size_t)b * S + (size_t)c * TT) * D + d;
    const float* xp = x + base;

    // Load the chunk's x values (coalesced per timestep; high MLP).
    float v[TT];
#pragma unroll
    for (int j = 0; j < TT; ++j) v[j] = xp[(size_t)j * D];

    // Local chunk EMA starting from 0 -> chunk-end value e.
    float e = 0.0f;
#pragma unroll
    for (int j = 0; j < TT; ++j) e = ALPHA * e + ONEM * v[j];

    const size_t sidx = ((size_t)b * NC + c) * D + d;
    volatile int* myflag = &g_flag[((size_t)b * NC + c) * NXB + blockIdx.x];

    float carry = 0.0f;

    if (c == 0) {
        // Chunk 0: local == inclusive. Publish directly.
        g_incl[sidx] = e;
        __threadfence();
        __syncthreads();
        if (tid == 0) *myflag = 2;
    } else {
        // Publish aggregate early so successors can make progress.
        g_agg[sidx] = e;
        __threadfence();
        __syncthreads();
        if (tid == 0) *myflag = 1;

        // Decoupled lookback: accumulate decayed aggregates backward until an
        // inclusive prefix is found. Each thread handles its own channel d;
        // flag loads broadcast from L2, so per-thread spinning is cheap.
        float factor = 1.0f;
        int j = c - 1;
        while (true) {
            volatile int* pf = &g_flag[((size_t)b * NC + j) * NXB + blockIdx.x];
            int st;
            do { st = *pf; } while (st == 0);
            __threadfence();  // acquire: order data loads after flag observation
            const size_t pidx = ((size_t)b * NC + j) * D + d;
            if (st == 2) {
                carry += factor * *((volatile float*)&g_incl[pidx]);
                break;
            } else {
                carry += factor * *((volatile float*)&g_agg[pidx]);
                factor *= DEC;
                --j;
            }
        }

        // Publish inclusive prefix: P_c = e + alpha^TT * P_{c-1}.
        if (c != NC - 1) {
            g_incl[sidx] = fmaf(DEC, carry, e);
            __threadfence();
            __syncthreads();
            if (tid == 0) *myflag = 2;
        }
    }

    // Final pass: exact reference recurrence seeded with the carry.
    float* op = out + base;
    float ema = carry;
#pragma unroll
    for (int j = 0; j < TT; ++j) {
        ema = ALPHA * ema + ONEM * v[j];
        op[(size_t)j * D] = ema;
    }
}

extern "C" void kernel_launch(void* const* d_in, const int* in_sizes, int n_in,
                              void* d_out, int out_size) {
    const float* x = (const float*)d_in[0];
    float* out = (float*)d_out;

    ema_reset<<<(B * NC * NXB + 255) / 256, 256>>>();
    dim3 grid(NXB, NC, B);
    ema_scan<<<grid, DBLK>>>(x, out);
}

// round 3
// speedup vs baseline: 1.1619x; 1.1619x over previous
#include <cuda_runtime.h>

// EMA scan: out[b,t,d] = a*out[b,t-1,d] + (1-a)*x[b,t,d], out[b,-1,d]=0
// Shapes fixed: B=4, S=4096, D=2048, fp32.
//
// Single-kernel exact scheme: one thread per channel walks the full sequence,
// carrying the EMA in a register. 8192 channels -> 128 CTAs x 64 threads,
// one CTA per SM. Memory latency hidden by a 32-deep register prefetch ring;
// the 4096-long dependent FMA chain (~16k cycles) is far below the 268 MB
// bandwidth floor (~48 us), so the kernel runs at streaming pace.

#define B 4
#define S 4096
#define D 2048
#define THREADS 64
#define PD 32                    // prefetch distance (<= ~55 outstanding LDG/warp)

__global__ void __launch_bounds__(THREADS) ema_walk(const float* __restrict__ x,
                                                    float* __restrict__ out) {
    const int d = blockIdx.x * THREADS + threadIdx.x;   // 0..D-1
    const int b = blockIdx.y;

    const size_t col = (size_t)b * S * D + d;
    const float* __restrict__ xp = x + col;
    float* __restrict__ op = out + col;

    const float a = 0.99f, om = 0.01f;

    // Prime the prefetch ring with the first PD timesteps.
    float v[PD];
#pragma unroll
    for (int j = 0; j < PD; ++j) v[j] = __ldg(&xp[(size_t)j * D]);

    float ema = 0.0f;

    // Main loop: while consuming block t..t+PD-1, stream in t+PD..t+2PD-1.
    // Prefetch loads are independent of the serial EMA chain, so the warp
    // keeps PD coalesced 128B loads in flight at all times.
    for (int t = 0; t < S - PD; t += PD) {
#pragma unroll
        for (int j = 0; j < PD; ++j) {
            float nv = __ldg(&xp[(size_t)(t + PD + j) * D]);
            ema = fmaf(a, ema, om * v[j]);
            op[(size_t)(t + j) * D] = ema;
            v[j] = nv;
        }
    }

    // Drain the last PD timesteps.
#pragma unroll
    for (int j = 0; j < PD; ++j) {
        ema = fmaf(a, ema, om * v[j]);
        op[(size_t)(S - PD + j) * D] = ema;
    }
}

extern "C" void kernel_launch(void* const* d_in, const int* in_sizes, int n_in,
                              void* d_out, int out_size) {
    const float* x = (const float*)d_in[0];
    float* out = (float*)d_out;

    dim3 grid(D / THREADS, B);   // (32, 4) = 128 CTAs, one per SM
    ema_walk<<<grid, THREADS>>>(x, out);
}